// round 8
// baseline (speedup 1.0000x reference)
#include <cuda_runtime.h>

#define T_LEN 1024
#define BATCH 4
#define EMB   1024
#define NH    16
#define HD    64
#define BH    (BATCH*NH)   // 64
#define NREL  33           // 2L+1

// Scratch (static device arrays: allocation-free per harness rules)
__device__ float g_q[BH * T_LEN * HD];        // tf32 bits, pre-scaled by 0.125*log2e
__device__ float g_k[BH * T_LEN * HD];        // tf32 bits
__device__ float g_v[BH * HD * T_LEN];        // tf32 bits, TRANSPOSED [bh][d][t]
__device__ float g_attn[T_LEN * BATCH * EMB]; // tf32 bits, [t*4+b][e]
__device__ float g_qin[4096 * 1024];          // tf32(query)
__device__ float g_win[3072 * 1024];          // tf32(w_in)
__device__ float g_wout[1024 * 1024];         // tf32(w_out)

__device__ __forceinline__ unsigned f2tf(float f) {
    unsigned u;
    asm("cvt.rna.tf32.f32 %0, %1;" : "=r"(u) : "f"(f));
    return u;
}

__device__ __forceinline__ float ex2(float x) {
    float y;
    asm("ex2.approx.ftz.f32 %0, %1;" : "=f"(y) : "f"(x));
    return y;
}

// D += A @ B  (m16n8k8, tf32 in, fp32 accum). c aliases d.
__device__ __forceinline__ void mma8(float* c, const unsigned* a, const unsigned* b) {
    asm volatile(
        "mma.sync.aligned.m16n8k8.row.col.f32.tf32.tf32.f32 "
        "{%0,%1,%2,%3}, {%4,%5,%6,%7}, {%8,%9}, {%0,%1,%2,%3};\n"
        : "+f"(c[0]), "+f"(c[1]), "+f"(c[2]), "+f"(c[3])
        : "r"(a[0]), "r"(a[1]), "r"(a[2]), "r"(a[3]), "r"(b[0]), "r"(b[1]));
}

__device__ __forceinline__ unsigned smem_u32(const void* p) {
    return (unsigned)__cvta_generic_to_shared(p);
}

__device__ __forceinline__ void ldsm4(unsigned* d, unsigned addr) {
    asm volatile(
        "ldmatrix.sync.aligned.m8n8.x4.shared.b16 {%0,%1,%2,%3}, [%4];"
        : "=r"(d[0]), "=r"(d[1]), "=r"(d[2]), "=r"(d[3]) : "r"(addr));
}

__device__ __forceinline__ void cpa16(unsigned dst, const void* src) {
    asm volatile("cp.async.cg.shared.global [%0], [%1], 16;"
                 :: "r"(dst), "l"(src));
}

// ---------------------------------------------------------------------------
// Elementwise fp32 -> tf32(rna) pre-conversion (bits stored in float array).
// ---------------------------------------------------------------------------
__global__ void __launch_bounds__(256)
cvt_tf32(const float* __restrict__ in, float* __restrict__ out_, int n4)
{
    const int i = blockIdx.x * 256 + threadIdx.x;
    if (i < n4) {
        float4 v = ((const float4*)in)[i];
        uint4 u = make_uint4(f2tf(v.x), f2tf(v.y), f2tf(v.z), f2tf(v.w));
        ((uint4*)out_)[i] = u;
    }
}

// ---------------------------------------------------------------------------
// TC GEMM (unchanged from round 7 except q scale absorbs log2e).
// ---------------------------------------------------------------------------
#define GSTG (128 * 36)

__global__ void __launch_bounds__(256, 2)
gemm_tc(const float* __restrict__ A, const float* __restrict__ B,
        const float* __restrict__ bias, float* __restrict__ Cout,
        int M, int N, int K, int mode)
{
    extern __shared__ unsigned sh[];
    unsigned* As = sh;               // [2][128*36], stride 36 (≡4 mod 32)
    unsigned* Bs = sh + 2 * GSTG;

    const int tid  = threadIdx.x;
    const int lane = tid & 31;
    const int warp = tid >> 5;
    const int wm   = (warp & 3) * 32;
    const int wn   = (warp >> 2) * 64;
    const int row0 = blockIdx.y * 128;
    const int col0 = blockIdx.x * 128;

    const int lr = tid >> 3;            // 0..31
    const int lk = (tid & 7) * 4;       // 0..28

    const int lrow = lane & 7;
    const int lb3  = (lane >> 3) & 1;
    const int lb4  = lane >> 4;
    unsigned aAddr[2], bAddr[4];
#pragma unroll
    for (int mt = 0; mt < 2; mt++)
        aAddr[mt] = smem_u32(&As[(wm + mt * 16 + lrow + lb3 * 8) * 36 + lb4 * 4]);
#pragma unroll
    for (int np = 0; np < 4; np++)
        bAddr[np] = smem_u32(&Bs[(wn + np * 16 + lb4 * 8 + lrow) * 36 + lb3 * 4]);

    float acc[2][8][4];
#pragma unroll
    for (int mt = 0; mt < 2; mt++)
#pragma unroll
        for (int nt = 0; nt < 8; nt++)
#pragma unroll
            for (int f = 0; f < 4; f++) acc[mt][nt][f] = 0.0f;

    const unsigned* aP = (const unsigned*)A + (size_t)row0 * K;
    const unsigned* bP = (const unsigned*)B + (size_t)col0 * K;

    uint4 pa[4], pb[4];
#pragma unroll
    for (int r = 0; r < 4; r++) {
        pa[r] = *(const uint4*)(aP + (size_t)(lr + 32 * r) * K + lk);
        pb[r] = *(const uint4*)(bP + (size_t)(lr + 32 * r) * K + lk);
    }
#pragma unroll
    for (int r = 0; r < 4; r++) {
        *(uint4*)&As[(lr + 32 * r) * 36 + lk] = pa[r];
        *(uint4*)&Bs[(lr + 32 * r) * 36 + lk] = pb[r];
    }
    __syncthreads();

    const int nC = K >> 5;
    for (int c = 0; c < nC; c++) {
        const unsigned soff = (c & 1) * (GSTG * 4);
        unsigned* An = As + ((c & 1) ^ 1) * GSTG;
        unsigned* Bn = Bs + ((c & 1) ^ 1) * GSTG;

        const bool more = (c + 1 < nC);
        if (more) {
            const int ko = (c + 1) * 32 + lk;
#pragma unroll
            for (int r = 0; r < 4; r++) {
                pa[r] = *(const uint4*)(aP + (size_t)(lr + 32 * r) * K + ko);
                pb[r] = *(const uint4*)(bP + (size_t)(lr + 32 * r) * K + ko);
            }
        }

#pragma unroll
        for (int ks = 0; ks < 4; ks++) {
            const unsigned ko = soff + ks * 32;
            unsigned a[2][4], bf[4][4];
            ldsm4(a[0], aAddr[0] + ko);
            ldsm4(a[1], aAddr[1] + ko);
#pragma unroll
            for (int np = 0; np < 4; np++) ldsm4(bf[np], bAddr[np] + ko);
#pragma unroll
            for (int np = 0; np < 4; np++) {
                mma8(acc[0][2 * np],     a[0], &bf[np][0]);
                mma8(acc[1][2 * np],     a[1], &bf[np][0]);
                mma8(acc[0][2 * np + 1], a[0], &bf[np][2]);
                mma8(acc[1][2 * np + 1], a[1], &bf[np][2]);
            }
        }

        if (more) {
#pragma unroll
            for (int r = 0; r < 4; r++) {
                *(uint4*)&An[(lr + 32 * r) * 36 + lk] = pa[r];
                *(uint4*)&Bn[(lr + 32 * r) * 36 + lk] = pb[r];
            }
        }
        __syncthreads();
    }

    const int q4 = lane & 3;
    const int g8 = lane >> 2;
#pragma unroll
    for (int mt = 0; mt < 2; mt++) {
#pragma unroll
        for (int rr = 0; rr < 2; rr++) {
            const int m = row0 + wm + mt * 16 + g8 + rr * 8;
#pragma unroll
            for (int nt = 0; nt < 8; nt++) {
#pragma unroll
                for (int cc = 0; cc < 2; cc++) {
                    const int n = col0 + wn + nt * 8 + 2 * q4 + cc;
                    float v = acc[mt][nt][rr * 2 + cc] + bias[n];
                    if (mode == 0) {
                        const int sec = n >> 10;
                        const int e = n & 1023;
                        const int h = e >> 6, d = e & 63;
                        const int t = m >> 2, b = m & 3;
                        const int bh = b * NH + h;
                        if (sec == 0)  // 0.125 * log2(e)
                            g_q[(bh * T_LEN + t) * HD + d] =
                                __uint_as_float(f2tf(v * 0.18033688f));
                        else if (sec == 1)
                            g_k[(bh * T_LEN + t) * HD + d] =
                                __uint_as_float(f2tf(v));
                        else
                            g_v[((size_t)bh * HD + d) * T_LEN + t] =
                                __uint_as_float(f2tf(v));
                    } else {
                        Cout[(size_t)m * N + n] = v;
                    }
                }
            }
        }
    }
}

// ---------------------------------------------------------------------------
// Flash attention, 128-row q-tiles, 4 warps x 32 rows, cp.async K/V pipeline.
// grid = (8 q-tiles, 64 heads), 128 threads. Base-2 softmax (q pre-scaled).
// ---------------------------------------------------------------------------
__global__ void __launch_bounds__(128)
attn_tc(const float* __restrict__ relk)
{
    extern __shared__ float sm[];
    unsigned* Qs = (unsigned*)sm;              // [128][68]
    unsigned* Ks = Qs + 128 * 68;              // [2][64][68]
    unsigned* Vs = Ks + 2 * 64 * 68;           // [2][64][68] rows=d, cols=s
    unsigned* Ps = Vs + 2 * 64 * 68;           // [128][68]
    float* qrs   = (float*)(Ps + 128 * 68);    // [128][33]
    unsigned* rels = Ps;                       // overlay [64][68], rows33-63 zero

    const int tid  = threadIdx.x;
    const int lane = tid & 31;
    const int warp = tid >> 5;                 // 0..3
    const int q4   = lane & 3;
    const int g8   = lane >> 2;                // 0..7
    const int bh   = blockIdx.y;
    const int tq0  = blockIdx.x * 128;
    const int m0   = warp * 32;

    const int lrow = lane & 7;
    const int lb3  = (lane >> 3) & 1;
    const int lb4  = lane >> 4;
    unsigned qAddr[2], pAddr[2], relAddr[3], kAddr[2][4], vAddr[2][4];
#pragma unroll
    for (int mf = 0; mf < 2; mf++) {
        qAddr[mf] = smem_u32(&Qs[(m0 + mf * 16 + lrow + lb3 * 8) * 68 + lb4 * 4]);
        pAddr[mf] = smem_u32(&Ps[(m0 + mf * 16 + lrow + lb3 * 8) * 68 + lb4 * 4]);
    }
#pragma unroll
    for (int np = 0; np < 3; np++)
        relAddr[np] = smem_u32(&rels[(np * 16 + lb4 * 8 + lrow) * 68 + lb3 * 4]);
#pragma unroll
    for (int st = 0; st < 2; st++)
#pragma unroll
        for (int np = 0; np < 4; np++) {
            kAddr[st][np] = smem_u32(&Ks[(st * 64 + np * 16 + lb4 * 8 + lrow) * 68 + lb3 * 4]);
            vAddr[st][np] = smem_u32(&Vs[(st * 64 + np * 16 + lb4 * 8 + lrow) * 68 + lb3 * 4]);
        }
    unsigned kSm[2], vSm[2];
#pragma unroll
    for (int st = 0; st < 2; st++) {
        kSm[st] = smem_u32(&Ks[st * 64 * 68]);
        vSm[st] = smem_u32(&Vs[st * 64 * 68]);
    }

    // stage Q (128x64, tf32) — verbatim
    {
        const uint4* qb = (const uint4*)(g_q + (size_t)(bh * T_LEN + tq0) * HD);
#pragma unroll 2
        for (int i = tid; i < 2048; i += 128)
            *(uint4*)&Qs[(i >> 4) * 68 + (i & 15) * 4] = qb[i];
    }
    // stage relation keys into overlay (tf32), zero-pad rows 33..63
    for (int i = tid; i < 64 * 68; i += 128) rels[i] = 0u;
    __syncthreads();
    for (int i = tid; i < NREL * 64; i += 128) {
        const int j = i >> 6, d = i & 63;
        rels[j * 68 + d] = f2tf(relk[j * EMB + d]);
    }
    __syncthreads();

    const float* kbase = g_k + (size_t)bh * T_LEN * HD;   // [t][d]
    const float* vbase = g_v + (size_t)bh * HD * T_LEN;   // [d][t]

    // issue K/V tile 0 into stage 0
    {
#pragma unroll
        for (int it = 0; it < 8; it++) {
            const int i = tid + 128 * it;
            const int r = i >> 4, c4 = (i & 15) * 4;
            cpa16(kSm[0] + (unsigned)(r * 68 + c4) * 4, kbase + (size_t)r * HD + c4);
            cpa16(vSm[0] + (unsigned)(r * 68 + c4) * 4, vbase + (size_t)r * T_LEN + c4);
        }
        asm volatile("cp.async.commit_group;");
    }

    // qr[r][j] = q[r] . rel[j] via MMA (j 0..32 within nt 0..5)
    {
        float sq[2][6][4];
#pragma unroll
        for (int mf = 0; mf < 2; mf++)
#pragma unroll
            for (int nt = 0; nt < 6; nt++)
#pragma unroll
                for (int f = 0; f < 4; f++) sq[mf][nt][f] = 0.0f;
#pragma unroll
        for (int ks = 0; ks < 8; ks++) {
            const unsigned ko = ks * 32;
            unsigned a0[4], a1[4];
            ldsm4(a0, qAddr[0] + ko);
            ldsm4(a1, qAddr[1] + ko);
#pragma unroll
            for (int np = 0; np < 3; np++) {
                unsigned bf[4];
                ldsm4(bf, relAddr[np] + ko);
                mma8(sq[0][2 * np],     a0, &bf[0]);
                mma8(sq[1][2 * np],     a1, &bf[0]);
                mma8(sq[0][2 * np + 1], a0, &bf[2]);
                mma8(sq[1][2 * np + 1], a1, &bf[2]);
            }
        }
#pragma unroll
        for (int mf = 0; mf < 2; mf++)
#pragma unroll
            for (int rid = 0; rid < 2; rid++) {
                const int rloc = m0 + mf * 16 + rid * 8 + g8;
#pragma unroll
                for (int nt = 0; nt < 6; nt++)
#pragma unroll
                    for (int cc = 0; cc < 2; cc++) {
                        const int j = nt * 8 + 2 * q4 + cc;
                        if (j < NREL)
                            qrs[rloc * NREL + j] = sq[mf][nt][rid * 2 + cc];
                    }
            }
    }

    float o[2][8][4];
#pragma unroll
    for (int mf = 0; mf < 2; mf++)
#pragma unroll
        for (int nt = 0; nt < 8; nt++)
#pragma unroll
            for (int f = 0; f < 4; f++) o[mf][nt][f] = 0.0f;
    float mrow[4] = {-1e30f, -1e30f, -1e30f, -1e30f};
    float lrw[4]  = {0.0f, 0.0f, 0.0f, 0.0f};

    for (int kt = 0; kt < 16; kt++) {
        const int s0 = kt * 64;
        const int st = kt & 1;

        if (kt + 1 < 16) {
            const float* kb = kbase + (size_t)(s0 + 64) * HD;
            const float* vb = vbase + (s0 + 64);
            const int sn = st ^ 1;
#pragma unroll
            for (int it = 0; it < 8; it++) {
                const int i = tid + 128 * it;
                const int r = i >> 4, c4 = (i & 15) * 4;
                cpa16(kSm[sn] + (unsigned)(r * 68 + c4) * 4, kb + (size_t)r * HD + c4);
                cpa16(vSm[sn] + (unsigned)(r * 68 + c4) * 4, vb + (size_t)r * T_LEN + c4);
            }
            asm volatile("cp.async.commit_group;");
            asm volatile("cp.async.wait_group 1;");
        } else {
            asm volatile("cp.async.wait_group 0;");
        }
        __syncthreads();   // tile kt resident; qrs ready (kt==0); P-overlay done

        // S = Q @ K^T : 32 rows x 64 cols per warp
        float s[2][8][4];
#pragma unroll
        for (int mf = 0; mf < 2; mf++)
#pragma unroll
            for (int nt = 0; nt < 8; nt++)
#pragma unroll
                for (int f = 0; f < 4; f++) s[mf][nt][f] = 0.0f;

#pragma unroll
        for (int ks = 0; ks < 8; ks++) {
            const unsigned ko = ks * 32;
            unsigned a0[4], a1[4];
            ldsm4(a0, qAddr[0] + ko);
            ldsm4(a1, qAddr[1] + ko);
#pragma unroll
            for (int np = 0; np < 4; np++) {
                unsigned bf[4];
                ldsm4(bf, kAddr[st][np] + ko);
                mma8(s[0][2 * np],     a0, &bf[0]);
                mma8(s[1][2 * np],     a1, &bf[0]);
                mma8(s[0][2 * np + 1], a0, &bf[2]);
                mma8(s[1][2 * np + 1], a1, &bf[2]);
            }
        }

        // bias + online softmax (4 row-groups per lane)
#pragma unroll
        for (int mf = 0; mf < 2; mf++) {
#pragma unroll
            for (int rid = 0; rid < 2; rid++) {
                const int rr = mf * 2 + rid;
                const int rloc = m0 + mf * 16 + rid * 8 + g8;
                const int rg = tq0 + rloc;
                const float* qr = &qrs[rloc * NREL];
                float vals[16];
                float mx = -1e30f;
                if (s0 - rg >= 16) {               // fully saturated high
                    const float b32 = qr[32];
#pragma unroll
                    for (int nt = 0; nt < 8; nt++)
#pragma unroll
                        for (int cc = 0; cc < 2; cc++) {
                            float v = s[mf][nt][rid * 2 + cc] + b32;
                            vals[nt * 2 + cc] = v;
                            mx = fmaxf(mx, v);
                        }
                } else if (rg - s0 >= 79) {        // fully saturated low
                    const float b0 = qr[0];
#pragma unroll
                    for (int nt = 0; nt < 8; nt++)
#pragma unroll
                        for (int cc = 0; cc < 2; cc++) {
                            float v = s[mf][nt][rid * 2 + cc] + b0;
                            vals[nt * 2 + cc] = v;
                            mx = fmaxf(mx, v);
                        }
                } else {
#pragma unroll
                    for (int nt = 0; nt < 8; nt++)
#pragma unroll
                        for (int cc = 0; cc < 2; cc++) {
                            const int sg = s0 + nt * 8 + 2 * q4 + cc;
                            int delta = min(max(sg - rg, -16), 16) + 16;
                            float v = s[mf][nt][rid * 2 + cc] + qr[delta];
                            vals[nt * 2 + cc] = v;
                            mx = fmaxf(mx, v);
                        }
                }
                mx = fmaxf(mx, __shfl_xor_sync(0xffffffffu, mx, 1));
                mx = fmaxf(mx, __shfl_xor_sync(0xffffffffu, mx, 2));
                const float mnew = fmaxf(mrow[rr], mx);
                const float alpha = ex2(mrow[rr] - mnew);
                float rs = 0.0f;
#pragma unroll
                for (int j = 0; j < 16; j++) {
                    vals[j] = ex2(vals[j] - mnew);
                    rs += vals[j];
                }
                rs += __shfl_xor_sync(0xffffffffu, rs, 1);
                rs += __shfl_xor_sync(0xffffffffu, rs, 2);
                lrw[rr] = lrw[rr] * alpha + rs;
                mrow[rr] = mnew;
#pragma unroll
                for (int nt = 0; nt < 8; nt++) {
                    o[mf][nt][rid * 2]     *= alpha;
                    o[mf][nt][rid * 2 + 1] *= alpha;
                }
#pragma unroll
                for (int nt = 0; nt < 8; nt++) {
                    const int cpos = nt * 8 + 2 * q4;
                    uint2 pw = make_uint2(f2tf(vals[nt * 2]), f2tf(vals[nt * 2 + 1]));
                    *(uint2*)&Ps[rloc * 68 + cpos] = pw;
                }
            }
        }
        __syncwarp();   // P produced/consumed within this warp only

        // O += P @ V
#pragma unroll
        for (int ks = 0; ks < 8; ks++) {
            const unsigned ko = ks * 32;
            unsigned a0[4], a1[4];
            ldsm4(a0, pAddr[0] + ko);
            ldsm4(a1, pAddr[1] + ko);
#pragma unroll
            for (int np = 0; np < 4; np++) {
                unsigned vf[4];
                ldsm4(vf, vAddr[st][np] + ko);
                mma8(o[0][2 * np],     a0, &vf[0]);
                mma8(o[1][2 * np],     a1, &vf[0]);
                mma8(o[0][2 * np + 1], a0, &vf[2]);
                mma8(o[1][2 * np + 1], a1, &vf[2]);
            }
        }
        __syncthreads();   // all warps done with stage st before it is refilled
    }

    // write attn (tf32 bits) in [t][b][e] layout
    const int b = bh >> 4, h = bh & 15;
#pragma unroll
    for (int mf = 0; mf < 2; mf++) {
#pragma unroll
        for (int rid = 0; rid < 2; rid++) {
            const int rr = mf * 2 + rid;
            const int t = tq0 + m0 + mf * 16 + rid * 8 + g8;
            const float inv = 1.0f / lrw[rr];
#pragma unroll
            for (int nt = 0; nt < 8; nt++) {
                const int d = nt * 8 + 2 * q4;
                uint2 w = make_uint2(f2tf(o[mf][nt][rid * 2] * inv),
                                     f2tf(o[mf][nt][rid * 2 + 1] * inv));
                *(uint2*)&g_attn[(t * BATCH + b) * EMB + h * HD + d] = w;
            }
        }
    }
}

// ---------------------------------------------------------------------------
extern "C" void kernel_launch(void* const* d_in, const int* in_sizes, int n_in,
                              void* d_out, int out_size)
{
    (void)in_sizes; (void)n_in; (void)out_size;
    const float* query = (const float*)d_in[0];   // [T,B,E]
    const float* w_in  = (const float*)d_in[1];   // [3E,E]
    const float* b_in  = (const float*)d_in[2];   // [3E]
    const float* relk  = (const float*)d_in[3];   // [33,E]
    const float* w_out = (const float*)d_in[4];   // [E,E]
    const float* b_out = (const float*)d_in[5];   // [E]
    float* out = (float*)d_out;                   // [T,B,E]

    float *qin, *win, *wout, *attn_ptr;
    cudaGetSymbolAddress((void**)&qin,  g_qin);
    cudaGetSymbolAddress((void**)&win,  g_win);
    cudaGetSymbolAddress((void**)&wout, g_wout);
    cudaGetSymbolAddress((void**)&attn_ptr, g_attn);

    // 0) one-time tf32 pre-conversion of fp32 operands
    cvt_tf32<<<4096, 256>>>(query, qin, 4096 * 1024 / 4);
    cvt_tf32<<<3072, 256>>>(w_in,  win, 3072 * 1024 / 4);
    cvt_tf32<<<1024, 256>>>(w_out, wout, 1024 * 1024 / 4);

    const size_t gemm_smem = (size_t)4 * GSTG * sizeof(unsigned);  // 73728 B
    cudaFuncSetAttribute(gemm_tc,
                         cudaFuncAttributeMaxDynamicSharedMemorySize,
                         (int)gemm_smem);

    // 1) fused QKV projection -> tf32 head-major q/k/v (V transposed)
    gemm_tc<<<dim3(24, 32), 256, gemm_smem>>>(
        qin, win, b_in, nullptr, 4096, 3072, 1024, 0);

    // 2) flash attention with relative bias
    const size_t attn_smem =
        (size_t)(128 * 68 + 2 * 64 * 68 + 2 * 64 * 68 + 128 * 68
                 + 128 * NREL) * sizeof(float);   // 156160 B
    cudaFuncSetAttribute(attn_tc,
                         cudaFuncAttributeMaxDynamicSharedMemorySize,
                         (int)attn_smem);
    attn_tc<<<dim3(8, 64), 128, attn_smem>>>(relk);

    // 3) output projection (writes fp32 final output)
    gemm_tc<<<dim3(8, 32), 256, gemm_smem>>>(
        attn_ptr, wout, b_out, out, 4096, 1024, 1024, 1);
}

// round 9
// speedup vs baseline: 1.0528x; 1.0528x over previous
#include <cuda_runtime.h>

#define T_LEN 1024
#define BATCH 4
#define EMB   1024
#define NH    16
#define HD    64
#define BH    (BATCH*NH)   // 64
#define NREL  33           // 2L+1

// Scratch (static device arrays: allocation-free per harness rules)
__device__ float g_q[BH * T_LEN * HD];        // tf32 bits, pre-scaled by 0.125*log2e
__device__ float g_k[BH * T_LEN * HD];        // tf32 bits
__device__ float g_v[BH * HD * T_LEN];        // tf32 bits, TRANSPOSED [bh][d][t]
__device__ float g_attn[T_LEN * BATCH * EMB]; // tf32 bits, [t*4+b][e]
__device__ float g_qin[4096 * 1024];          // tf32(query)
__device__ float g_win[3072 * 1024];          // tf32(w_in)
__device__ float g_wout[1024 * 1024];         // tf32(w_out)

__device__ __forceinline__ unsigned f2tf(float f) {
    unsigned u;
    asm("cvt.rna.tf32.f32 %0, %1;" : "=r"(u) : "f"(f));
    return u;
}

__device__ __forceinline__ float ex2(float x) {
    float y;
    asm("ex2.approx.ftz.f32 %0, %1;" : "=f"(y) : "f"(x));
    return y;
}

// D += A @ B  (m16n8k8, tf32 in, fp32 accum). c aliases d.
__device__ __forceinline__ void mma8(float* c, const unsigned* a, const unsigned* b) {
    asm volatile(
        "mma.sync.aligned.m16n8k8.row.col.f32.tf32.tf32.f32 "
        "{%0,%1,%2,%3}, {%4,%5,%6,%7}, {%8,%9}, {%0,%1,%2,%3};\n"
        : "+f"(c[0]), "+f"(c[1]), "+f"(c[2]), "+f"(c[3])
        : "r"(a[0]), "r"(a[1]), "r"(a[2]), "r"(a[3]), "r"(b[0]), "r"(b[1]));
}

__device__ __forceinline__ unsigned smem_u32(const void* p) {
    return (unsigned)__cvta_generic_to_shared(p);
}

__device__ __forceinline__ void ldsm4(unsigned* d, unsigned addr) {
    asm volatile(
        "ldmatrix.sync.aligned.m8n8.x4.shared.b16 {%0,%1,%2,%3}, [%4];"
        : "=r"(d[0]), "=r"(d[1]), "=r"(d[2]), "=r"(d[3]) : "r"(addr));
}

// ---------------------------------------------------------------------------
// Elementwise fp32 -> tf32(rna) pre-conversion (bits stored in float array).
// ---------------------------------------------------------------------------
__global__ void __launch_bounds__(256)
cvt_tf32(const float* __restrict__ in, float* __restrict__ out_, int n4)
{
    const int i = blockIdx.x * 256 + threadIdx.x;
    if (i < n4) {
        float4 v = ((const float4*)in)[i];
        uint4 u = make_uint4(f2tf(v.x), f2tf(v.y), f2tf(v.z), f2tf(v.w));
        ((uint4*)out_)[i] = u;
    }
}

// ---------------------------------------------------------------------------
// TC GEMM: C[M,N] = A[M,K] * B[N,K]^T + bias[N].  A,B hold tf32 bit patterns.
// mode 0: scatter tf32-rounded q/k/v (q scaled by 0.125*log2e, V TRANSPOSED).
// mode 1: write fp32 Cout.  Block 128x128, K-chunk 32, 8 warps, 2 CTAs/SM.
// ---------------------------------------------------------------------------
#define GSTG (128 * 36)

__global__ void __launch_bounds__(256, 2)
gemm_tc(const float* __restrict__ A, const float* __restrict__ B,
        const float* __restrict__ bias, float* __restrict__ Cout,
        int M, int N, int K, int mode)
{
    extern __shared__ unsigned sh[];
    unsigned* As = sh;               // [2][128*36], stride 36 (≡4 mod 32)
    unsigned* Bs = sh + 2 * GSTG;

    const int tid  = threadIdx.x;
    const int lane = tid & 31;
    const int warp = tid >> 5;
    const int wm   = (warp & 3) * 32;
    const int wn   = (warp >> 2) * 64;
    const int row0 = blockIdx.y * 128;
    const int col0 = blockIdx.x * 128;

    const int lr = tid >> 3;            // 0..31
    const int lk = (tid & 7) * 4;       // 0..28

    const int lrow = lane & 7;
    const int lb3  = (lane >> 3) & 1;
    const int lb4  = lane >> 4;
    unsigned aAddr[2], bAddr[4];
#pragma unroll
    for (int mt = 0; mt < 2; mt++)
        aAddr[mt] = smem_u32(&As[(wm + mt * 16 + lrow + lb3 * 8) * 36 + lb4 * 4]);
#pragma unroll
    for (int np = 0; np < 4; np++)
        bAddr[np] = smem_u32(&Bs[(wn + np * 16 + lb4 * 8 + lrow) * 36 + lb3 * 4]);

    float acc[2][8][4];
#pragma unroll
    for (int mt = 0; mt < 2; mt++)
#pragma unroll
        for (int nt = 0; nt < 8; nt++)
#pragma unroll
            for (int f = 0; f < 4; f++) acc[mt][nt][f] = 0.0f;

    const unsigned* aP = (const unsigned*)A + (size_t)row0 * K;
    const unsigned* bP = (const unsigned*)B + (size_t)col0 * K;

    uint4 pa[4], pb[4];
#pragma unroll
    for (int r = 0; r < 4; r++) {
        pa[r] = *(const uint4*)(aP + (size_t)(lr + 32 * r) * K + lk);
        pb[r] = *(const uint4*)(bP + (size_t)(lr + 32 * r) * K + lk);
    }
#pragma unroll
    for (int r = 0; r < 4; r++) {
        *(uint4*)&As[(lr + 32 * r) * 36 + lk] = pa[r];
        *(uint4*)&Bs[(lr + 32 * r) * 36 + lk] = pb[r];
    }
    __syncthreads();

    const int nC = K >> 5;
    for (int c = 0; c < nC; c++) {
        const unsigned soff = (c & 1) * (GSTG * 4);
        unsigned* An = As + ((c & 1) ^ 1) * GSTG;
        unsigned* Bn = Bs + ((c & 1) ^ 1) * GSTG;

        const bool more = (c + 1 < nC);
        if (more) {
            const int ko = (c + 1) * 32 + lk;
#pragma unroll
            for (int r = 0; r < 4; r++) {
                pa[r] = *(const uint4*)(aP + (size_t)(lr + 32 * r) * K + ko);
                pb[r] = *(const uint4*)(bP + (size_t)(lr + 32 * r) * K + ko);
            }
        }

#pragma unroll
        for (int ks = 0; ks < 4; ks++) {
            const unsigned ko = soff + ks * 32;
            unsigned a[2][4], bf[4][4];
            ldsm4(a[0], aAddr[0] + ko);
            ldsm4(a[1], aAddr[1] + ko);
#pragma unroll
            for (int np = 0; np < 4; np++) ldsm4(bf[np], bAddr[np] + ko);
#pragma unroll
            for (int np = 0; np < 4; np++) {
                mma8(acc[0][2 * np],     a[0], &bf[np][0]);
                mma8(acc[1][2 * np],     a[1], &bf[np][0]);
                mma8(acc[0][2 * np + 1], a[0], &bf[np][2]);
                mma8(acc[1][2 * np + 1], a[1], &bf[np][2]);
            }
        }

        if (more) {
#pragma unroll
            for (int r = 0; r < 4; r++) {
                *(uint4*)&An[(lr + 32 * r) * 36 + lk] = pa[r];
                *(uint4*)&Bn[(lr + 32 * r) * 36 + lk] = pb[r];
            }
        }
        __syncthreads();
    }

    const int q4 = lane & 3;
    const int g8 = lane >> 2;
#pragma unroll
    for (int mt = 0; mt < 2; mt++) {
#pragma unroll
        for (int rr = 0; rr < 2; rr++) {
            const int m = row0 + wm + mt * 16 + g8 + rr * 8;
#pragma unroll
            for (int nt = 0; nt < 8; nt++) {
#pragma unroll
                for (int cc = 0; cc < 2; cc++) {
                    const int n = col0 + wn + nt * 8 + 2 * q4 + cc;
                    float v = acc[mt][nt][rr * 2 + cc] + bias[n];
                    if (mode == 0) {
                        const int sec = n >> 10;
                        const int e = n & 1023;
                        const int h = e >> 6, d = e & 63;
                        const int t = m >> 2, b = m & 3;
                        const int bh = b * NH + h;
                        if (sec == 0)  // 0.125 * log2(e)
                            g_q[(bh * T_LEN + t) * HD + d] =
                                __uint_as_float(f2tf(v * 0.18033688f));
                        else if (sec == 1)
                            g_k[(bh * T_LEN + t) * HD + d] =
                                __uint_as_float(f2tf(v));
                        else  // V transposed: [bh][d][t]
                            g_v[((size_t)bh * HD + d) * T_LEN + t] =
                                __uint_as_float(f2tf(v));
                    } else {
                        Cout[(size_t)m * N + n] = v;
                    }
                }
            }
        }
    }
}

// ---------------------------------------------------------------------------
// Flash attention (round-7 shape: 64-row q-tiles, 4 warps x 16 rows, register
// K/V prefetch, 2 CTAs/SM) + base-2 softmax + saturation fast path + MMA qr.
// grid = (16 q-tiles, 64 heads), 128 threads.
// ---------------------------------------------------------------------------
__global__ void __launch_bounds__(128)
attn_tc(const float* __restrict__ relk)
{
    extern __shared__ float sm[];
    unsigned* Qs = (unsigned*)sm;             // [64][68]  rows=t, cols=d
    unsigned* Ks = Qs + 64 * 68;              // [64][68]  rows=s, cols=d
    unsigned* Vs = Ks + 64 * 68;              // [64][68]  rows=d, cols=s
    unsigned* Ps = Vs + 64 * 68;              // [64][68]  rows=t, cols=s
    float* qrs   = (float*)(Ps + 64 * 68);    // [64][33]
    unsigned* rels = Ps;                      // tf32 overlay [64][68], rows>=33 zero

    const int tid  = threadIdx.x;
    const int lane = tid & 31;
    const int warp = tid >> 5;                // 0..3
    const int q4   = lane & 3;
    const int g8   = lane >> 2;               // 0..7
    const int bh   = blockIdx.y;
    const int tq0  = blockIdx.x * 64;
    const int m0   = warp * 16;

    const int lrow = lane & 7;
    const int lb3  = (lane >> 3) & 1;
    const int lb4  = lane >> 4;
    const unsigned qAddr = smem_u32(&Qs[(m0 + lrow + lb3 * 8) * 68 + lb4 * 4]);
    const unsigned pAddr = smem_u32(&Ps[(m0 + lrow + lb3 * 8) * 68 + lb4 * 4]);
    unsigned kAddr[4], vAddr[4], relAddr[3];
#pragma unroll
    for (int np = 0; np < 4; np++) {
        kAddr[np] = smem_u32(&Ks[(np * 16 + lb4 * 8 + lrow) * 68 + lb3 * 4]);
        vAddr[np] = smem_u32(&Vs[(np * 16 + lb4 * 8 + lrow) * 68 + lb3 * 4]);
    }
#pragma unroll
    for (int np = 0; np < 3; np++)
        relAddr[np] = smem_u32(&rels[(np * 16 + lb4 * 8 + lrow) * 68 + lb3 * 4]);

    // load Q tile (64x64, already tf32)
    {
        const uint4* qb = (const uint4*)(g_q + (size_t)(bh * T_LEN + tq0) * HD);
#pragma unroll 2
        for (int i = tid; i < 1024; i += 128)
            *(uint4*)&Qs[(i >> 4) * 68 + (i & 15) * 4] = qb[i];
    }
    // relation keys (tf32) into Ps overlay; rows 33..63 zero
    for (int i = tid; i < 64 * 68; i += 128) rels[i] = 0u;
    __syncthreads();
    for (int i = tid; i < NREL * 64; i += 128) {
        const int j = i >> 6, d = i & 63;
        rels[j * 68 + d] = f2tf(relk[j * EMB + d]);
    }
    __syncthreads();

    // qr[r][j] = q[r] . rel[j] via MMA (j in 0..47, keep j<33)
    {
        float sq[6][4];
#pragma unroll
        for (int nt = 0; nt < 6; nt++)
#pragma unroll
            for (int f = 0; f < 4; f++) sq[nt][f] = 0.0f;
#pragma unroll
        for (int ks = 0; ks < 8; ks++) {
            const unsigned ko = ks * 32;
            unsigned a[4];
            ldsm4(a, qAddr + ko);
#pragma unroll
            for (int np = 0; np < 3; np++) {
                unsigned bf[4];
                ldsm4(bf, relAddr[np] + ko);
                mma8(sq[2 * np],     a, &bf[0]);
                mma8(sq[2 * np + 1], a, &bf[2]);
            }
        }
#pragma unroll
        for (int rid = 0; rid < 2; rid++) {
            const int rloc = m0 + rid * 8 + g8;
#pragma unroll
            for (int nt = 0; nt < 6; nt++)
#pragma unroll
                for (int cc = 0; cc < 2; cc++) {
                    const int j = nt * 8 + 2 * q4 + cc;
                    if (j < NREL) qrs[rloc * NREL + j] = sq[nt][rid * 2 + cc];
                }
        }
    }

    const uint4* kbase = (const uint4*)(g_k + (size_t)bh * T_LEN * HD);
    const float* vbase = g_v + (size_t)bh * HD * T_LEN;   // [d][t]

    // prefetch tile 0 into registers
    uint4 pk[8], pv[8];
#pragma unroll
    for (int it = 0; it < 8; it++) {
        const int i = tid + 128 * it;
        const int r = i >> 4, c4 = (i & 15) * 4;
        pk[it] = kbase[i];
        pv[it] = *(const uint4*)(vbase + (size_t)r * T_LEN + c4);
    }

    float o[8][4];
#pragma unroll
    for (int nt = 0; nt < 8; nt++)
#pragma unroll
        for (int f = 0; f < 4; f++) o[nt][f] = 0.0f;
    float mrow[2] = {-1e30f, -1e30f};
    float lrw[2]  = {0.0f, 0.0f};

    __syncthreads();   // qr writes visible; rel overlay consumption complete

    for (int kt = 0; kt < 16; kt++) {
        const int s0 = kt * 64;

        // store prefetched tile: Ks rows=s cols=d; Vs rows=d cols=s
#pragma unroll
        for (int it = 0; it < 8; it++) {
            const int i = tid + 128 * it;
            const int r = i >> 4, c4 = (i & 15) * 4;
            *(uint4*)&Ks[r * 68 + c4] = pk[it];
            *(uint4*)&Vs[r * 68 + c4] = pv[it];
        }
        __syncthreads();

        // prefetch next tile
        if (kt + 1 < 16) {
            const uint4* kb = kbase + (size_t)(s0 + 64) * (HD / 4);
#pragma unroll
            for (int it = 0; it < 8; it++) {
                const int i = tid + 128 * it;
                const int r = i >> 4, c4 = (i & 15) * 4;
                pk[it] = kb[i];
                pv[it] = *(const uint4*)(vbase + (size_t)r * T_LEN + s0 + 64 + c4);
            }
        }

        // S = Q @ K^T  (warp's 16 rows x 64 cols) — all via ldmatrix
        float s[8][4];
#pragma unroll
        for (int nt = 0; nt < 8; nt++)
#pragma unroll
            for (int f = 0; f < 4; f++) s[nt][f] = 0.0f;

#pragma unroll
        for (int ks = 0; ks < 8; ks++) {
            const unsigned ko = ks * 32;
            unsigned a[4];
            ldsm4(a, qAddr + ko);
#pragma unroll
            for (int np = 0; np < 4; np++) {
                unsigned bf[4];
                ldsm4(bf, kAddr[np] + ko);
                mma8(s[2 * np],     a, &bf[0]);
                mma8(s[2 * np + 1], a, &bf[2]);
            }
        }

        // bias + online softmax, base-2 (2 rows/lane; 4 lanes/row: xor 1,2)
#pragma unroll
        for (int rid = 0; rid < 2; rid++) {
            const int rloc = m0 + rid * 8 + g8;
            const int rg = tq0 + rloc;
            const float* qr = &qrs[rloc * NREL];
            float vals[16];
            float mx = -1e30f;
            if (s0 - rg >= 16) {               // whole tile right-saturated
                const float b32 = qr[32];
#pragma unroll
                for (int nt = 0; nt < 8; nt++)
#pragma unroll
                    for (int cc = 0; cc < 2; cc++) {
                        float v = s[nt][rid * 2 + cc] + b32;
                        vals[nt * 2 + cc] = v;
                        mx = fmaxf(mx, v);
                    }
            } else if (rg - s0 >= 79) {        // whole tile left-saturated
                const float b0 = qr[0];
#pragma unroll
                for (int nt = 0; nt < 8; nt++)
#pragma unroll
                    for (int cc = 0; cc < 2; cc++) {
                        float v = s[nt][rid * 2 + cc] + b0;
                        vals[nt * 2 + cc] = v;
                        mx = fmaxf(mx, v);
                    }
            } else {
#pragma unroll
                for (int nt = 0; nt < 8; nt++)
#pragma unroll
                    for (int cc = 0; cc < 2; cc++) {
                        const int sg = s0 + nt * 8 + 2 * q4 + cc;
                        int delta = min(max(sg - rg, -16), 16) + 16;
                        float v = s[nt][rid * 2 + cc] + qr[delta];
                        vals[nt * 2 + cc] = v;
                        mx = fmaxf(mx, v);
                    }
            }
            mx = fmaxf(mx, __shfl_xor_sync(0xffffffffu, mx, 1));
            mx = fmaxf(mx, __shfl_xor_sync(0xffffffffu, mx, 2));
            const float mnew = fmaxf(mrow[rid], mx);
            const float alpha = ex2(mrow[rid] - mnew);
            float rs = 0.0f;
#pragma unroll
            for (int j = 0; j < 16; j++) {
                vals[j] = ex2(vals[j] - mnew);
                rs += vals[j];
            }
            rs += __shfl_xor_sync(0xffffffffu, rs, 1);
            rs += __shfl_xor_sync(0xffffffffu, rs, 2);
            lrw[rid] = lrw[rid] * alpha + rs;
            mrow[rid] = mnew;
#pragma unroll
            for (int nt = 0; nt < 8; nt++) {
                o[nt][rid * 2]     *= alpha;
                o[nt][rid * 2 + 1] *= alpha;
            }
#pragma unroll
            for (int nt = 0; nt < 8; nt++) {
                const int cpos = nt * 8 + 2 * q4;
                uint2 pw = make_uint2(f2tf(vals[nt * 2]), f2tf(vals[nt * 2 + 1]));
                *(uint2*)&Ps[rloc * 68 + cpos] = pw;
            }
        }
        __syncwarp();   // P produced/consumed within this warp only

        // O += P @ V  (P and V via ldmatrix; Vs rows=d(n), cols=s(k))
#pragma unroll
        for (int ks = 0; ks < 8; ks++) {
            const unsigned ko = ks * 32;
            unsigned a[4];
            ldsm4(a, pAddr + ko);
#pragma unroll
            for (int np = 0; np < 4; np++) {
                unsigned vf[4];
                ldsm4(vf, vAddr[np] + ko);
                mma8(o[2 * np],     a, &vf[0]);
                mma8(o[2 * np + 1], a, &vf[2]);
            }
        }
        __syncthreads();   // done reading Ks/Vs; safe to overwrite next iter
    }

    // write attn (tf32 bits) in [t][b][e] layout
    const int b = bh >> 4, h = bh & 15;
#pragma unroll
    for (int rid = 0; rid < 2; rid++) {
        const int t = tq0 + m0 + rid * 8 + g8;
        const float inv = 1.0f / lrw[rid];
#pragma unroll
        for (int nt = 0; nt < 8; nt++) {
            const int d = nt * 8 + 2 * q4;
            uint2 w = make_uint2(f2tf(o[nt][rid * 2] * inv),
                                 f2tf(o[nt][rid * 2 + 1] * inv));
            *(uint2*)&g_attn[(t * BATCH + b) * EMB + h * HD + d] = w;
        }
    }
}

// ---------------------------------------------------------------------------
extern "C" void kernel_launch(void* const* d_in, const int* in_sizes, int n_in,
                              void* d_out, int out_size)
{
    (void)in_sizes; (void)n_in; (void)out_size;
    const float* query = (const float*)d_in[0];   // [T,B,E]
    const float* w_in  = (const float*)d_in[1];   // [3E,E]
    const float* b_in  = (const float*)d_in[2];   // [3E]
    const float* relk  = (const float*)d_in[3];   // [33,E]
    const float* w_out = (const float*)d_in[4];   // [E,E]
    const float* b_out = (const float*)d_in[5];   // [E]
    float* out = (float*)d_out;                   // [T,B,E]

    float *qin, *win, *wout, *attn_ptr;
    cudaGetSymbolAddress((void**)&qin,  g_qin);
    cudaGetSymbolAddress((void**)&win,  g_win);
    cudaGetSymbolAddress((void**)&wout, g_wout);
    cudaGetSymbolAddress((void**)&attn_ptr, g_attn);

    // 0) one-time tf32 pre-conversion of fp32 operands
    cvt_tf32<<<4096, 256>>>(query, qin, 4096 * 1024 / 4);
    cvt_tf32<<<3072, 256>>>(w_in,  win, 3072 * 1024 / 4);
    cvt_tf32<<<1024, 256>>>(w_out, wout, 1024 * 1024 / 4);

    const size_t gemm_smem = (size_t)4 * GSTG * sizeof(unsigned);  // 73728 B
    cudaFuncSetAttribute(gemm_tc,
                         cudaFuncAttributeMaxDynamicSharedMemorySize,
                         (int)gemm_smem);

    // 1) fused QKV projection -> tf32 head-major q/k/v (V transposed)
    gemm_tc<<<dim3(24, 32), 256, gemm_smem>>>(
        qin, win, b_in, nullptr, 4096, 3072, 1024, 0);

    // 2) flash attention with relative bias
    const size_t attn_smem =
        (size_t)(4 * 64 * 68 + 64 * NREL) * sizeof(float);   // 78080 B
    cudaFuncSetAttribute(attn_tc,
                         cudaFuncAttributeMaxDynamicSharedMemorySize,
                         (int)attn_smem);
    attn_tc<<<dim3(16, 64), 128, attn_smem>>>(relk);

    // 3) output projection (writes fp32 final output)
    gemm_tc<<<dim3(8, 32), 256, gemm_smem>>>(
        attn_ptr, wout, b_out, out, 4096, 1024, 1024, 1);
}